// round 7
// baseline (speedup 1.0000x reference)
#include <cuda_runtime.h>
#include <math.h>

#define NMAX 50000
#define EMAX 800000

__device__ __forceinline__ float tanh_fast(float x) {
    float y;
    asm("tanh.approx.f32 %0, %1;" : "=f"(y) : "f"(x));
    return y;
}
__device__ __forceinline__ float sigmoid_fast(float x) {
    return 0.5f * tanh_fast(0.5f * x) + 0.5f;
}

// ---------------- scratch (device globals; zero-initialized at module load) ----------
__device__ __align__(16) float g_gx[NMAX * 96];      // gconv(x), t-major: [t][node][f]
__device__ __align__(16) float g_h0[NMAX * 64];
__device__ __align__(16) float g_h1[NMAX * 64];
__device__ __align__(16) float g_gpair[NMAX * 128];  // [gconv(h0) | gconv(h1)]
__device__ __align__(16) float g_rh[NMAX * 64];      // r * h
__device__ __align__(16) float g_grh[NMAX * 64];     // gconv(r*h)
__device__ __align__(16) float g_z[NMAX * 64];
__device__ int   g_rowptr[NMAX + 1];
__device__ int   g_off[NMAX];
__device__ __align__(8) int2 g_edge[EMAX];           // (src, w bits)

// NOTE: h0/h1/gpair/rowptr must be zero at entry. They are zero-initialized at
// context creation, and cleanup_kernel (last launch) re-zeroes them, so the
// invariant holds across the correctness call and every graph replay.

__global__ void hist_kernel(const int* __restrict__ dst, int E) {
    int e = blockIdx.x * blockDim.x + threadIdx.x;
    if (e < E) atomicAdd(&g_rowptr[dst[e] + 1], 1);
}

// single-block inclusive scan of g_rowptr[0..n]; also writes g_off
__global__ void scan_kernel(int n) {
    __shared__ int buf[1024];
    __shared__ int carry;
    if (threadIdx.x == 0) carry = 0;
    __syncthreads();
    for (int base = 0; base < n + 1; base += 1024) {
        int i = base + threadIdx.x;
        int v = (i < n + 1) ? g_rowptr[i] : 0;
        buf[threadIdx.x] = v;
        __syncthreads();
        for (int ofs = 1; ofs < 1024; ofs <<= 1) {
            int t = (threadIdx.x >= ofs) ? buf[threadIdx.x - ofs] : 0;
            __syncthreads();
            buf[threadIdx.x] += t;
            __syncthreads();
        }
        int inc = buf[threadIdx.x] + carry;
        if (i < n + 1) {
            g_rowptr[i] = inc;
            if (i < n) g_off[i] = inc;
        }
        __syncthreads();
        if (threadIdx.x == 1023) carry = inc;
        __syncthreads();
    }
}

__global__ void scatter_kernel(const int* __restrict__ src, const int* __restrict__ dst,
                               const float* __restrict__ w, int E) {
    int e = blockIdx.x * blockDim.x + threadIdx.x;
    if (e < E) {
        int p = atomicAdd(&g_off[dst[e]], 1);
        g_edge[p] = make_int2(src[e], __float_as_int(w[e]));
    }
}

// ---------------- graph convolutions (warp per node, CSR) ----------------
// writes t-major: g_gx[t*N*8 + node*8 + f]
__global__ void gconv_x(const float* __restrict__ x, int N) {
    int node = blockIdx.x * (blockDim.x >> 5) + (threadIdx.x >> 5);
    if (node >= N) return;
    int lane = threadIdx.x & 31;
    int s = g_rowptr[node], e = g_rowptr[node + 1];
    float a0 = 0.f, a1 = 0.f, a2 = 0.f;
    for (int i = s; i < e; i++) {
        int2 em = __ldg(&g_edge[i]);
        float w = __int_as_float(em.y);
        const float* f = x + (size_t)em.x * 96;
        a0 += w * __ldg(f + lane);
        a1 += w * __ldg(f + lane + 32);
        a2 += w * __ldg(f + lane + 64);
    }
    size_t N8 = (size_t)N * 8;
#pragma unroll
    for (int j = 0; j < 3; j++) {
        int v = lane + j * 32;
        float a = (j == 0) ? a0 : (j == 1) ? a1 : a2;
        g_gx[(size_t)(v % 12) * N8 + (size_t)node * 8 + (v / 12)] = a;
    }
}

__global__ void gconv64_k(const float* __restrict__ feat, float* __restrict__ out, int N) {
    int node = blockIdx.x * (blockDim.x >> 5) + (threadIdx.x >> 5);
    if (node >= N) return;
    int lane = threadIdx.x & 31;
    int s = g_rowptr[node], e = g_rowptr[node + 1];
    float ax = 0.f, ay = 0.f;
    int i = s;
    for (; i + 3 < e; i += 4) {
        int2 e0 = __ldg(&g_edge[i]),     e1 = __ldg(&g_edge[i + 1]);
        int2 e2 = __ldg(&g_edge[i + 2]), e3 = __ldg(&g_edge[i + 3]);
        float2 f0 = __ldg(((const float2*)(feat + (size_t)e0.x * 64)) + lane);
        float2 f1 = __ldg(((const float2*)(feat + (size_t)e1.x * 64)) + lane);
        float2 f2 = __ldg(((const float2*)(feat + (size_t)e2.x * 64)) + lane);
        float2 f3 = __ldg(((const float2*)(feat + (size_t)e3.x * 64)) + lane);
        float w0 = __int_as_float(e0.y), w1 = __int_as_float(e1.y);
        float w2 = __int_as_float(e2.y), w3 = __int_as_float(e3.y);
        ax += w0 * f0.x; ay += w0 * f0.y;
        ax += w1 * f1.x; ay += w1 * f1.y;
        ax += w2 * f2.x; ay += w2 * f2.y;
        ax += w3 * f3.x; ay += w3 * f3.y;
    }
    for (; i < e; i++) {
        int2 e0 = __ldg(&g_edge[i]);
        float w0 = __int_as_float(e0.y);
        float2 f0 = __ldg(((const float2*)(feat + (size_t)e0.x * 64)) + lane);
        ax += w0 * f0.x; ay += w0 * f0.y;
    }
    ((float2*)(out + (size_t)node * 64))[lane] = make_float2(ax, ay);
}

// aggregate two 64-col tables in one edge pass -> out row of 128 ([a | b])
__global__ void gconv_dual_k(const float* __restrict__ fa, const float* __restrict__ fb,
                             float* __restrict__ out, int N) {
    int node = blockIdx.x * (blockDim.x >> 5) + (threadIdx.x >> 5);
    if (node >= N) return;
    int lane = threadIdx.x & 31;
    int s = g_rowptr[node], e = g_rowptr[node + 1];
    float ax = 0.f, ay = 0.f, bx = 0.f, by = 0.f;
    int i = s;
    for (; i + 1 < e; i += 2) {
        int2 e0 = __ldg(&g_edge[i]), e1 = __ldg(&g_edge[i + 1]);
        float w0 = __int_as_float(e0.y), w1 = __int_as_float(e1.y);
        float2 fa0 = __ldg(((const float2*)(fa + (size_t)e0.x * 64)) + lane);
        float2 fb0 = __ldg(((const float2*)(fb + (size_t)e0.x * 64)) + lane);
        float2 fa1 = __ldg(((const float2*)(fa + (size_t)e1.x * 64)) + lane);
        float2 fb1 = __ldg(((const float2*)(fb + (size_t)e1.x * 64)) + lane);
        ax += w0 * fa0.x; ay += w0 * fa0.y; bx += w0 * fb0.x; by += w0 * fb0.y;
        ax += w1 * fa1.x; ay += w1 * fa1.y; bx += w1 * fb1.x; by += w1 * fb1.y;
    }
    if (i < e) {
        int2 e0 = __ldg(&g_edge[i]);
        float w0 = __int_as_float(e0.y);
        float2 fa0 = __ldg(((const float2*)(fa + (size_t)e0.x * 64)) + lane);
        float2 fb0 = __ldg(((const float2*)(fb + (size_t)e0.x * 64)) + lane);
        ax += w0 * fa0.x; ay += w0 * fa0.y; bx += w0 * fb0.x; by += w0 * fb0.y;
    }
    ((float2*)(out + (size_t)node * 128))[lane]       = make_float2(ax, ay);
    ((float2*)(out + (size_t)node * 128 + 64))[lane]  = make_float2(bx, by);
}

// ============ gate GEMM: 64 rows x 128 cols, 256 threads, thread tile 4x8 ============
// rz = sigmoid([A1|A2] @ W + b); cols 0..63 -> rh = rz*h, cols 64..127 -> z
__global__ void __launch_bounds__(256) gate_kernel(
        const float* __restrict__ A1, int lda1, int K1,
        const float* __restrict__ A2, int lda2, int K2,
        const float* __restrict__ W, const float* __restrict__ bias,
        const float* __restrict__ h,
        float* __restrict__ rh, float* __restrict__ z, int nrows) {
    extern __shared__ float sh[];
    const int K = K1 + K2;
    float* SW = sh;            // K x 128
    float* SA = sh + K * 128;  // 64 x K
    int tid = threadIdx.x;
    for (int idx = tid; idx < K * 128; idx += 256) SW[idx] = W[idx];
    int row0 = blockIdx.x * 64;
    {
        int wid = tid >> 5, lane = tid & 31;
        for (int r = wid; r < 64; r += 8) {
            int grow = row0 + r;
            if (grow < nrows) {
                for (int k = lane; k < K; k += 32)
                    SA[r * K + k] = (k < K1) ? __ldg(&A1[(size_t)grow * lda1 + k])
                                             : __ldg(&A2[(size_t)grow * lda2 + (k - K1)]);
            } else {
                for (int k = lane; k < K; k += 32) SA[r * K + k] = 0.f;
            }
        }
    }
    __syncthreads();
    int colg = (tid & 15) * 8, rowg = (tid >> 4) * 4;
    float acc[4][8];
#pragma unroll
    for (int r = 0; r < 4; r++)
#pragma unroll
        for (int c = 0; c < 8; c++) acc[r][c] = 0.f;
    for (int k = 0; k < K; k += 4) {
        float4 wlo[4], whi[4];
#pragma unroll
        for (int kk = 0; kk < 4; kk++) {
            wlo[kk] = *(const float4*)&SW[(k + kk) * 128 + colg];
            whi[kk] = *(const float4*)&SW[(k + kk) * 128 + colg + 4];
        }
#pragma unroll
        for (int r = 0; r < 4; r++) {
            float4 a = *(const float4*)&SA[(rowg + r) * K + k];
#pragma unroll
            for (int kk = 0; kk < 4; kk++) {
                float av = (kk == 0) ? a.x : (kk == 1) ? a.y : (kk == 2) ? a.z : a.w;
                acc[r][0] += av * wlo[kk].x; acc[r][1] += av * wlo[kk].y;
                acc[r][2] += av * wlo[kk].z; acc[r][3] += av * wlo[kk].w;
                acc[r][4] += av * whi[kk].x; acc[r][5] += av * whi[kk].y;
                acc[r][6] += av * whi[kk].z; acc[r][7] += av * whi[kk].w;
            }
        }
    }
    float4 blo = *(const float4*)&bias[colg];
    float4 bhi = *(const float4*)&bias[colg + 4];
    bool isz = (colg >= 64);
#pragma unroll
    for (int r = 0; r < 4; r++) {
        int grow = row0 + rowg + r;
        if (grow >= nrows) break;
        float4 vlo, vhi;
        vlo.x = sigmoid_fast(acc[r][0] + blo.x);
        vlo.y = sigmoid_fast(acc[r][1] + blo.y);
        vlo.z = sigmoid_fast(acc[r][2] + blo.z);
        vlo.w = sigmoid_fast(acc[r][3] + blo.w);
        vhi.x = sigmoid_fast(acc[r][4] + bhi.x);
        vhi.y = sigmoid_fast(acc[r][5] + bhi.y);
        vhi.z = sigmoid_fast(acc[r][6] + bhi.z);
        vhi.w = sigmoid_fast(acc[r][7] + bhi.w);
        if (!isz) {
            float4 hlo = *(const float4*)&h[(size_t)grow * 64 + colg];
            float4 hhi = *(const float4*)&h[(size_t)grow * 64 + colg + 4];
            vlo.x *= hlo.x; vlo.y *= hlo.y; vlo.z *= hlo.z; vlo.w *= hlo.w;
            vhi.x *= hhi.x; vhi.y *= hhi.y; vhi.z *= hhi.z; vhi.w *= hhi.w;
            *(float4*)&rh[(size_t)grow * 64 + colg]     = vlo;
            *(float4*)&rh[(size_t)grow * 64 + colg + 4] = vhi;
        } else {
            *(float4*)&z[(size_t)grow * 64 + (colg - 64)]     = vlo;
            *(float4*)&z[(size_t)grow * 64 + (colg - 64) + 4] = vhi;
        }
    }
}

// ============ cand GEMM: 128 rows x 64 cols, 256 threads, thread tile 8x4 ============
// c = tanh([A1|A2] @ W + b); h = z*h + (1-z)*c
__global__ void __launch_bounds__(256) cand_kernel(
        const float* __restrict__ A1, int lda1, int K1,
        const float* __restrict__ A2, int lda2, int K2,
        const float* __restrict__ W, const float* __restrict__ bias,
        const float* __restrict__ z,
        float* __restrict__ h, int nrows) {
    extern __shared__ float sh[];
    const int K = K1 + K2;
    float* SW = sh;           // K x 64
    float* SA = sh + K * 64;  // 128 x K
    int tid = threadIdx.x;
    for (int idx = tid; idx < K * 64; idx += 256) SW[idx] = W[idx];
    int row0 = blockIdx.x * 128;
    {
        int wid = tid >> 5, lane = tid & 31;
        for (int r = wid; r < 128; r += 8) {
            int grow = row0 + r;
            if (grow < nrows) {
                for (int k = lane; k < K; k += 32)
                    SA[r * K + k] = (k < K1) ? __ldg(&A1[(size_t)grow * lda1 + k])
                                             : __ldg(&A2[(size_t)grow * lda2 + (k - K1)]);
            } else {
                for (int k = lane; k < K; k += 32) SA[r * K + k] = 0.f;
            }
        }
    }
    __syncthreads();
    int colg = (tid & 15) * 4, rowg = (tid >> 4) * 8;
    float acc[8][4];
#pragma unroll
    for (int r = 0; r < 8; r++) { acc[r][0] = acc[r][1] = acc[r][2] = acc[r][3] = 0.f; }
    for (int k = 0; k < K; k += 4) {
        float4 w0 = *(const float4*)&SW[(k + 0) * 64 + colg];
        float4 w1 = *(const float4*)&SW[(k + 1) * 64 + colg];
        float4 w2 = *(const float4*)&SW[(k + 2) * 64 + colg];
        float4 w3 = *(const float4*)&SW[(k + 3) * 64 + colg];
#pragma unroll
        for (int r = 0; r < 8; r++) {
            float4 a = *(const float4*)&SA[(rowg + r) * K + k];
            acc[r][0] += a.x * w0.x; acc[r][1] += a.x * w0.y; acc[r][2] += a.x * w0.z; acc[r][3] += a.x * w0.w;
            acc[r][0] += a.y * w1.x; acc[r][1] += a.y * w1.y; acc[r][2] += a.y * w1.z; acc[r][3] += a.y * w1.w;
            acc[r][0] += a.z * w2.x; acc[r][1] += a.z * w2.y; acc[r][2] += a.z * w2.z; acc[r][3] += a.z * w2.w;
            acc[r][0] += a.w * w3.x; acc[r][1] += a.w * w3.y; acc[r][2] += a.w * w3.z; acc[r][3] += a.w * w3.w;
        }
    }
    float4 b4 = *(const float4*)&bias[colg];
#pragma unroll
    for (int r = 0; r < 8; r++) {
        int grow = row0 + rowg + r;
        if (grow >= nrows) break;
        float4 c4;
        c4.x = tanh_fast(acc[r][0] + b4.x);
        c4.y = tanh_fast(acc[r][1] + b4.y);
        c4.z = tanh_fast(acc[r][2] + b4.z);
        c4.w = tanh_fast(acc[r][3] + b4.w);
        float4 z4 = *(const float4*)&z[(size_t)grow * 64 + colg];
        float4 h4 = *(const float4*)&h[(size_t)grow * 64 + colg];
        h4.x = z4.x * h4.x + (1.f - z4.x) * c4.x;
        h4.y = z4.y * h4.y + (1.f - z4.y) * c4.y;
        h4.z = z4.z * h4.z + (1.f - z4.z) * c4.z;
        h4.w = z4.w * h4.w + (1.f - z4.w) * c4.w;
        *(float4*)&h[(size_t)grow * 64 + colg] = h4;
    }
}

// ---------------- output: out = h1 @ Wout + bout (Wout is 64x1) ----------------
__global__ void out_kernel(const float* __restrict__ h1, const float* __restrict__ Wout,
                           const float* __restrict__ bout, float* __restrict__ out, int N) {
    int node = blockIdx.x * (blockDim.x >> 5) + (threadIdx.x >> 5);
    if (node >= N) return;
    int lane = threadIdx.x & 31;
    float v = h1[(size_t)node * 64 + lane] * __ldg(&Wout[lane]) +
              h1[(size_t)node * 64 + lane + 32] * __ldg(&Wout[lane + 32]);
#pragma unroll
    for (int o = 16; o > 0; o >>= 1) v += __shfl_xor_sync(0xffffffffu, v, o);
    if (lane == 0) out[node] = v + bout[0];
}

// ---------------- cleanup: restore zero-state invariant for the next call ----------
__global__ void cleanup_kernel(int N) {
    int stride = gridDim.x * blockDim.x;
    for (int i = blockIdx.x * blockDim.x + threadIdx.x; i < N * 128; i += stride) {
        g_gpair[i] = 0.f;
        if (i < N * 64) { g_h0[i] = 0.f; g_h1[i] = 0.f; }
        if (i < N + 1) g_rowptr[i] = 0;
    }
}

// ---------------- launch ----------------
extern "C" void kernel_launch(void* const* d_in, const int* in_sizes, int n_in,
                              void* d_out, int out_size) {
    const float* x   = (const float*)d_in[0];
    const int*   ei  = (const int*)d_in[1];
    const float* ew  = (const float*)d_in[2];
    const float* Wg0 = (const float*)d_in[3];
    const float* bg0 = (const float*)d_in[4];
    const float* Wc0 = (const float*)d_in[5];
    const float* bc0 = (const float*)d_in[6];
    const float* Wg1 = (const float*)d_in[7];
    const float* bg1 = (const float*)d_in[8];
    const float* Wc1 = (const float*)d_in[9];
    const float* bc1 = (const float*)d_in[10];
    const float* Wout = (const float*)d_in[11];
    const float* bout = (const float*)d_in[12];

    int N = in_sizes[0] / 96;   // F=8, T=12
    int E = in_sizes[2];
    if (N > NMAX || E > EMAX) return;
    const int* src = ei;
    const int* dst = ei + E;

    float *p_gx, *p_h0, *p_h1, *p_gpair, *p_rh, *p_grh, *p_z;
    cudaGetSymbolAddress((void**)&p_gx, g_gx);
    cudaGetSymbolAddress((void**)&p_h0, g_h0);
    cudaGetSymbolAddress((void**)&p_h1, g_h1);
    cudaGetSymbolAddress((void**)&p_gpair, g_gpair);
    cudaGetSymbolAddress((void**)&p_rh, g_rh);
    cudaGetSymbolAddress((void**)&p_grh, g_grh);
    cudaGetSymbolAddress((void**)&p_z, g_z);

    cudaFuncSetAttribute(gate_kernel, cudaFuncAttributeMaxDynamicSharedMemorySize, 98304);
    cudaFuncSetAttribute(cand_kernel, cudaFuncAttributeMaxDynamicSharedMemorySize, 98304);

    // CSR build (rowptr enters zeroed; cleanup_kernel restores that at the end)
    hist_kernel<<<(E + 255) / 256, 256>>>(dst, E);              // 0
    scan_kernel<<<1, 1024>>>(N);                                // 1
    scatter_kernel<<<(E + 255) / 256, 256>>>(src, dst, ew, E);  // 2

    int gblocks = (N + 7) / 8;
    gconv_x<<<gblocks, 256>>>(x, N);                            // 3 (ncu-profiled slot)

    size_t N8 = (size_t)N * 8;
    int rb64  = (N + 63) / 64;
    int rb128 = (N + 127) / 128;
    size_t smg72  = (size_t)(72 * 128 + 64 * 72) * 4;    // 55296
    size_t smg128 = (size_t)(128 * 128 + 64 * 128) * 4;  // 98304
    size_t smc72  = (size_t)(72 * 64 + 128 * 72) * 4;    // 55296
    size_t smc128 = (size_t)(128 * 64 + 128 * 128) * 4;  // 98304

    for (int t = 0; t < 12; t++) {
        // ---- cell 0 ----  (gconv(h0_{t-1}) lives in gpair[:, 0:64] from prior dual pass)
        gate_kernel<<<rb64, 256, smg72>>>(p_gx + (size_t)t * N8, 8, 8,
                                          p_gpair, 128, 64,
                                          Wg0, bg0, p_h0, p_rh, p_z, N);
        gconv64_k<<<gblocks, 256>>>(p_rh, p_grh, N);
        cand_kernel<<<rb128, 256, smc72>>>(p_gx + (size_t)t * N8, 8, 8,
                                           p_grh, 64, 64,
                                           Wc0, bc0, p_z, p_h0, N);  // h0 <- new h0
        // ---- cell 1 ----
        gconv_dual_k<<<gblocks, 256>>>(p_h0, p_h1, p_gpair, N);  // [gconv(h0_new) | gconv(h1)]
        gate_kernel<<<rb64, 256, smg128>>>(p_gpair, 128, 128,
                                           p_grh, 64, 0,
                                           Wg1, bg1, p_h1, p_rh, p_z, N);
        gconv64_k<<<gblocks, 256>>>(p_rh, p_grh, N);
        cand_kernel<<<rb128, 256, smc128>>>(p_gpair, 128, 64,
                                            p_grh, 64, 64,
                                            Wc1, bc1, p_z, p_h1, N);  // h1 <- new h1
    }

    out_kernel<<<gblocks, 256>>>(p_h1, Wout, bout, (float*)d_out, N);
    cleanup_kernel<<<512, 256>>>(N);
}

// round 10
// speedup vs baseline: 1.1628x; 1.1628x over previous
#include <cuda_runtime.h>
#include <cuda_fp16.h>
#include <math.h>

#define NMAX 50000
#define EMAX 800000

__device__ __forceinline__ float tanh_fast(float x) {
    float y;
    asm("tanh.approx.f32 %0, %1;" : "=f"(y) : "f"(x));
    return y;
}
__device__ __forceinline__ float sigmoid_fast(float x) {
    return 0.5f * tanh_fast(0.5f * x) + 0.5f;
}

// ---------------- scratch (device globals; zero-initialized at module load) ----------
__device__ __align__(16) float  g_gx[NMAX * 96];      // gconv(x), t-major: [t][node][8]
__device__ __align__(16) float  g_h0[NMAX * 64];
__device__ __align__(16) float  g_h1[NMAX * 64];
__device__ __align__(16) float  g_gpair[NMAX * 128];  // [gconv(h0) | gconv(h1)] fp32
__device__ __align__(16) float  g_grh[NMAX * 64];     // gconv(r*h) fp32
__device__ __align__(16) float  g_z[NMAX * 64];
__device__ __align__(8)  __half2 g_rh16[NMAX * 32];   // r*h, fp16 (gconv input)
__device__ __align__(16) uint2   g_hpk[NMAX * 32];    // packed {h0 half2, h1 half2} per lane
__device__ int   g_rowptr[NMAX + 1];
__device__ int   g_off[NMAX];
__device__ __align__(8) int2 g_edge[EMAX];            // (src, w bits)

// NOTE: h0/h1/gpair/hpk/rowptr must be zero at entry. Zero-initialized at module
// load; cleanup_kernel (last launch) re-zeroes them, so the invariant holds
// across the correctness call and every graph replay.

__global__ void hist_kernel(const int* __restrict__ dst, int E) {
    int e = blockIdx.x * blockDim.x + threadIdx.x;
    if (e < E) atomicAdd(&g_rowptr[dst[e] + 1], 1);
}

// single-block inclusive scan of g_rowptr[0..n]; also writes g_off
__global__ void scan_kernel(int n) {
    __shared__ int buf[1024];
    __shared__ int carry;
    if (threadIdx.x == 0) carry = 0;
    __syncthreads();
    for (int base = 0; base < n + 1; base += 1024) {
        int i = base + threadIdx.x;
        int v = (i < n + 1) ? g_rowptr[i] : 0;
        buf[threadIdx.x] = v;
        __syncthreads();
        for (int ofs = 1; ofs < 1024; ofs <<= 1) {
            int t = (threadIdx.x >= ofs) ? buf[threadIdx.x - ofs] : 0;
            __syncthreads();
            buf[threadIdx.x] += t;
            __syncthreads();
        }
        int inc = buf[threadIdx.x] + carry;
        if (i < n + 1) {
            g_rowptr[i] = inc;
            if (i < n) g_off[i] = inc;
        }
        __syncthreads();
        if (threadIdx.x == 1023) carry = inc;
        __syncthreads();
    }
}

__global__ void scatter_kernel(const int* __restrict__ src, const int* __restrict__ dst,
                               const float* __restrict__ w, int E) {
    int e = blockIdx.x * blockDim.x + threadIdx.x;
    if (e < E) {
        int p = atomicAdd(&g_off[dst[e]], 1);
        g_edge[p] = make_int2(src[e], __float_as_int(w[e]));
    }
}

// ---------------- graph convolutions (warp per node, CSR) ----------------
// writes t-major: g_gx[t*N*8 + node*8 + f]
__global__ void gconv_x(const float* __restrict__ x, int N) {
    int node = blockIdx.x * (blockDim.x >> 5) + (threadIdx.x >> 5);
    if (node >= N) return;
    int lane = threadIdx.x & 31;
    int s = g_rowptr[node], e = g_rowptr[node + 1];
    float a0 = 0.f, a1 = 0.f, a2 = 0.f;
    for (int i = s; i < e; i++) {
        int2 em = __ldg(&g_edge[i]);
        float w = __int_as_float(em.y);
        const float* f = x + (size_t)em.x * 96;
        a0 += w * __ldg(f + lane);
        a1 += w * __ldg(f + lane + 32);
        a2 += w * __ldg(f + lane + 64);
    }
    size_t N8 = (size_t)N * 8;
#pragma unroll
    for (int j = 0; j < 3; j++) {
        int v = lane + j * 32;
        float a = (j == 0) ? a0 : (j == 1) ? a1 : a2;
        g_gx[(size_t)(v % 12) * N8 + (size_t)node * 8 + (v / 12)] = a;
    }
}

// 64-col aggregation over fp16 table g_rh16 -> fp32 g_grh
__global__ void gconv64_h16(int N) {
    int node = blockIdx.x * (blockDim.x >> 5) + (threadIdx.x >> 5);
    if (node >= N) return;
    int lane = threadIdx.x & 31;
    int s = g_rowptr[node], e = g_rowptr[node + 1];
    float ax = 0.f, ay = 0.f;
    int i = s;
    for (; i + 3 < e; i += 4) {
        int2 e0 = __ldg(&g_edge[i]),     e1 = __ldg(&g_edge[i + 1]);
        int2 e2 = __ldg(&g_edge[i + 2]), e3 = __ldg(&g_edge[i + 3]);
        float2 f0 = __half22float2(__ldg(&g_rh16[(size_t)e0.x * 32 + lane]));
        float2 f1 = __half22float2(__ldg(&g_rh16[(size_t)e1.x * 32 + lane]));
        float2 f2 = __half22float2(__ldg(&g_rh16[(size_t)e2.x * 32 + lane]));
        float2 f3 = __half22float2(__ldg(&g_rh16[(size_t)e3.x * 32 + lane]));
        float w0 = __int_as_float(e0.y), w1 = __int_as_float(e1.y);
        float w2 = __int_as_float(e2.y), w3 = __int_as_float(e3.y);
        ax += w0 * f0.x; ay += w0 * f0.y;
        ax += w1 * f1.x; ay += w1 * f1.y;
        ax += w2 * f2.x; ay += w2 * f2.y;
        ax += w3 * f3.x; ay += w3 * f3.y;
    }
    for (; i < e; i++) {
        int2 e0 = __ldg(&g_edge[i]);
        float w0 = __int_as_float(e0.y);
        float2 f0 = __half22float2(__ldg(&g_rh16[(size_t)e0.x * 32 + lane]));
        ax += w0 * f0.x; ay += w0 * f0.y;
    }
    ((float2*)(g_grh + (size_t)node * 64))[lane] = make_float2(ax, ay);
}

// dual aggregation over packed fp16 {h0,h1} table -> fp32 gpair row of 128
__global__ void gconv_dual_h16(int N) {
    int node = blockIdx.x * (blockDim.x >> 5) + (threadIdx.x >> 5);
    if (node >= N) return;
    int lane = threadIdx.x & 31;
    int s = g_rowptr[node], e = g_rowptr[node + 1];
    float ax = 0.f, ay = 0.f, bx = 0.f, by = 0.f;
    int i = s;
    for (; i + 1 < e; i += 2) {
        int2 e0 = __ldg(&g_edge[i]), e1 = __ldg(&g_edge[i + 1]);
        uint2 p0 = __ldg(&g_hpk[(size_t)e0.x * 32 + lane]);
        uint2 p1 = __ldg(&g_hpk[(size_t)e1.x * 32 + lane]);
        float w0 = __int_as_float(e0.y), w1 = __int_as_float(e1.y);
        float2 a0 = __half22float2(*(__half2*)&p0.x), b0 = __half22float2(*(__half2*)&p0.y);
        float2 a1 = __half22float2(*(__half2*)&p1.x), b1 = __half22float2(*(__half2*)&p1.y);
        ax += w0 * a0.x; ay += w0 * a0.y; bx += w0 * b0.x; by += w0 * b0.y;
        ax += w1 * a1.x; ay += w1 * a1.y; bx += w1 * b1.x; by += w1 * b1.y;
    }
    if (i < e) {
        int2 e0 = __ldg(&g_edge[i]);
        uint2 p0 = __ldg(&g_hpk[(size_t)e0.x * 32 + lane]);
        float w0 = __int_as_float(e0.y);
        float2 a0 = __half22float2(*(__half2*)&p0.x), b0 = __half22float2(*(__half2*)&p0.y);
        ax += w0 * a0.x; ay += w0 * a0.y; bx += w0 * b0.x; by += w0 * b0.y;
    }
    ((float2*)(g_gpair + (size_t)node * 128))[lane]      = make_float2(ax, ay);
    ((float2*)(g_gpair + (size_t)node * 128 + 64))[lane] = make_float2(bx, by);
}

// ============ gate GEMM: 64x64 tile, grid.y=2 selects column half ============
// cy=0 -> cols 0..63: rh16 = sigmoid(.)*h (fp16); cy=1 -> cols 64..127: z (fp32)
__global__ void __launch_bounds__(256, 3) gate_kernel(
        const float* __restrict__ A1, int lda1, int K1,
        const float* __restrict__ A2, int lda2, int K2,
        const float* __restrict__ W, const float* __restrict__ bias,
        const float* __restrict__ h,
        float* __restrict__ z, int nrows) {
    extern __shared__ float sh[];
    const int K = K1 + K2;
    float* SW = sh;          // K x 64
    float* SA = sh + K * 64; // 64 x K
    int tid = threadIdx.x;
    int cy = blockIdx.y;
    for (int idx = tid; idx < K * 64; idx += 256) {
        int k = idx >> 6, c = idx & 63;
        SW[idx] = W[k * 128 + cy * 64 + c];
    }
    int row0 = blockIdx.x * 64;
    {
        int wid = tid >> 5, lane = tid & 31;
        for (int r = wid; r < 64; r += 8) {
            int grow = row0 + r;
            if (grow < nrows) {
                for (int k = lane; k < K; k += 32)
                    SA[r * K + k] = (k < K1) ? __ldg(&A1[(size_t)grow * lda1 + k])
                                             : __ldg(&A2[(size_t)grow * lda2 + (k - K1)]);
            } else {
                for (int k = lane; k < K; k += 32) SA[r * K + k] = 0.f;
            }
        }
    }
    __syncthreads();
    int colg = (tid & 15) * 4, rowg = (tid >> 4) * 4;
    float acc[4][4];
#pragma unroll
    for (int r = 0; r < 4; r++) { acc[r][0] = acc[r][1] = acc[r][2] = acc[r][3] = 0.f; }
#pragma unroll 2
    for (int k = 0; k < K; k += 4) {
        float4 w0 = *(const float4*)&SW[(k + 0) * 64 + colg];
        float4 w1 = *(const float4*)&SW[(k + 1) * 64 + colg];
        float4 w2 = *(const float4*)&SW[(k + 2) * 64 + colg];
        float4 w3 = *(const float4*)&SW[(k + 3) * 64 + colg];
#pragma unroll
        for (int r = 0; r < 4; r++) {
            float4 a = *(const float4*)&SA[(rowg + r) * K + k];
            acc[r][0] += a.x * w0.x; acc[r][1] += a.x * w0.y; acc[r][2] += a.x * w0.z; acc[r][3] += a.x * w0.w;
            acc[r][0] += a.y * w1.x; acc[r][1] += a.y * w1.y; acc[r][2] += a.y * w1.z; acc[r][3] += a.y * w1.w;
            acc[r][0] += a.z * w2.x; acc[r][1] += a.z * w2.y; acc[r][2] += a.z * w2.z; acc[r][3] += a.z * w2.w;
            acc[r][0] += a.w * w3.x; acc[r][1] += a.w * w3.y; acc[r][2] += a.w * w3.z; acc[r][3] += a.w * w3.w;
        }
    }
    float4 b4 = *(const float4*)&bias[cy * 64 + colg];
#pragma unroll
    for (int r = 0; r < 4; r++) {
        int grow = row0 + rowg + r;
        if (grow >= nrows) break;
        float4 v;
        v.x = sigmoid_fast(acc[r][0] + b4.x);
        v.y = sigmoid_fast(acc[r][1] + b4.y);
        v.z = sigmoid_fast(acc[r][2] + b4.z);
        v.w = sigmoid_fast(acc[r][3] + b4.w);
        if (cy == 0) {
            float4 h4 = *(const float4*)&h[(size_t)grow * 64 + colg];
            __half2 q0 = __floats2half2_rn(v.x * h4.x, v.y * h4.y);
            __half2 q1 = __floats2half2_rn(v.z * h4.z, v.w * h4.w);
            g_rh16[(size_t)grow * 32 + (colg >> 1)]     = q0;
            g_rh16[(size_t)grow * 32 + (colg >> 1) + 1] = q1;
        } else {
            *(float4*)&z[(size_t)grow * 64 + colg] = v;
        }
    }
}

// ============ cand GEMM: 64x64 tile ============
// c = tanh([A1|A2] @ W + b); h = z*h + (1-z)*c; also write fp16 copy into hpack slot
__global__ void __launch_bounds__(256, 3) cand_kernel(
        const float* __restrict__ A1, int lda1, int K1,
        const float* __restrict__ A2, int lda2, int K2,
        const float* __restrict__ W, const float* __restrict__ bias,
        const float* __restrict__ z,
        float* __restrict__ h, int slot, int nrows) {
    extern __shared__ float sh[];
    const int K = K1 + K2;
    float* SW = sh;          // K x 64
    float* SA = sh + K * 64; // 64 x K
    int tid = threadIdx.x;
    for (int idx = tid; idx < K * 64; idx += 256) SW[idx] = W[idx];
    int row0 = blockIdx.x * 64;
    {
        int wid = tid >> 5, lane = tid & 31;
        for (int r = wid; r < 64; r += 8) {
            int grow = row0 + r;
            if (grow < nrows) {
                for (int k = lane; k < K; k += 32)
                    SA[r * K + k] = (k < K1) ? __ldg(&A1[(size_t)grow * lda1 + k])
                                             : __ldg(&A2[(size_t)grow * lda2 + (k - K1)]);
            } else {
                for (int k = lane; k < K; k += 32) SA[r * K + k] = 0.f;
            }
        }
    }
    __syncthreads();
    int colg = (tid & 15) * 4, rowg = (tid >> 4) * 4;
    float acc[4][4];
#pragma unroll
    for (int r = 0; r < 4; r++) { acc[r][0] = acc[r][1] = acc[r][2] = acc[r][3] = 0.f; }
#pragma unroll 2
    for (int k = 0; k < K; k += 4) {
        float4 w0 = *(const float4*)&SW[(k + 0) * 64 + colg];
        float4 w1 = *(const float4*)&SW[(k + 1) * 64 + colg];
        float4 w2 = *(const float4*)&SW[(k + 2) * 64 + colg];
        float4 w3 = *(const float4*)&SW[(k + 3) * 64 + colg];
#pragma unroll
        for (int r = 0; r < 4; r++) {
            float4 a = *(const float4*)&SA[(rowg + r) * K + k];
            acc[r][0] += a.x * w0.x; acc[r][1] += a.x * w0.y; acc[r][2] += a.x * w0.z; acc[r][3] += a.x * w0.w;
            acc[r][0] += a.y * w1.x; acc[r][1] += a.y * w1.y; acc[r][2] += a.y * w1.z; acc[r][3] += a.y * w1.w;
            acc[r][0] += a.z * w2.x; acc[r][1] += a.z * w2.y; acc[r][2] += a.z * w2.z; acc[r][3] += a.z * w2.w;
            acc[r][0] += a.w * w3.x; acc[r][1] += a.w * w3.y; acc[r][2] += a.w * w3.z; acc[r][3] += a.w * w3.w;
        }
    }
    float4 b4 = *(const float4*)&bias[colg];
#pragma unroll
    for (int r = 0; r < 4; r++) {
        int grow = row0 + rowg + r;
        if (grow >= nrows) break;
        float4 c4;
        c4.x = tanh_fast(acc[r][0] + b4.x);
        c4.y = tanh_fast(acc[r][1] + b4.y);
        c4.z = tanh_fast(acc[r][2] + b4.z);
        c4.w = tanh_fast(acc[r][3] + b4.w);
        float4 z4 = *(const float4*)&z[(size_t)grow * 64 + colg];
        float4 h4 = *(const float4*)&h[(size_t)grow * 64 + colg];
        h4.x = z4.x * h4.x + (1.f - z4.x) * c4.x;
        h4.y = z4.y * h4.y + (1.f - z4.y) * c4.y;
        h4.z = z4.z * h4.z + (1.f - z4.z) * c4.z;
        h4.w = z4.w * h4.w + (1.f - z4.w) * c4.w;
        *(float4*)&h[(size_t)grow * 64 + colg] = h4;
        // fp16 copy into packed table (slot 0 = h0, slot 1 = h1)
        __half2 q0 = __floats2half2_rn(h4.x, h4.y);
        __half2 q1 = __floats2half2_rn(h4.z, h4.w);
        unsigned* hp = (unsigned*)&g_hpk[(size_t)grow * 32 + (colg >> 1)];
        hp[slot]     = *(unsigned*)&q0;
        hp[2 + slot] = *(unsigned*)&q1;
    }
}

// ---------------- output: out = h1 @ Wout + bout (Wout is 64x1) ----------------
__global__ void out_kernel(const float* __restrict__ h1, const float* __restrict__ Wout,
                           const float* __restrict__ bout, float* __restrict__ out, int N) {
    int node = blockIdx.x * (blockDim.x >> 5) + (threadIdx.x >> 5);
    if (node >= N) return;
    int lane = threadIdx.x & 31;
    float v = h1[(size_t)node * 64 + lane] * __ldg(&Wout[lane]) +
              h1[(size_t)node * 64 + lane + 32] * __ldg(&Wout[lane + 32]);
#pragma unroll
    for (int o = 16; o > 0; o >>= 1) v += __shfl_xor_sync(0xffffffffu, v, o);
    if (lane == 0) out[node] = v + bout[0];
}

// ---------------- cleanup: restore zero-state invariant for the next call ----------
__global__ void cleanup_kernel(int N) {
    int stride = gridDim.x * blockDim.x;
    float2 zz = make_float2(0.f, 0.f);
    for (int i = blockIdx.x * blockDim.x + threadIdx.x; i < N * 64; i += stride) {
        ((float2*)g_gpair)[i] = zz;           // N*128 floats
        if (i < N * 32) {
            ((float2*)g_h0)[i] = zz;          // N*64 floats
            ((float2*)g_h1)[i] = zz;
            g_hpk[i] = make_uint2(0u, 0u);    // N*32 uint2
        }
        if (i < N + 1) g_rowptr[i] = 0;
    }
}

// ---------------- launch ----------------
extern "C" void kernel_launch(void* const* d_in, const int* in_sizes, int n_in,
                              void* d_out, int out_size) {
    const float* x   = (const float*)d_in[0];
    const int*   ei  = (const int*)d_in[1];
    const float* ew  = (const float*)d_in[2];
    const float* Wg0 = (const float*)d_in[3];
    const float* bg0 = (const float*)d_in[4];
    const float* Wc0 = (const float*)d_in[5];
    const float* bc0 = (const float*)d_in[6];
    const float* Wg1 = (const float*)d_in[7];
    const float* bg1 = (const float*)d_in[8];
    const float* Wc1 = (const float*)d_in[9];
    const float* bc1 = (const float*)d_in[10];
    const float* Wout = (const float*)d_in[11];
    const float* bout = (const float*)d_in[12];

    int N = in_sizes[0] / 96;   // F=8, T=12
    int E = in_sizes[2];
    if (N > NMAX || E > EMAX) return;
    const int* src = ei;
    const int* dst = ei + E;

    float *p_gx, *p_h0, *p_h1, *p_gpair, *p_grh, *p_z;
    cudaGetSymbolAddress((void**)&p_gx, g_gx);
    cudaGetSymbolAddress((void**)&p_h0, g_h0);
    cudaGetSymbolAddress((void**)&p_h1, g_h1);
    cudaGetSymbolAddress((void**)&p_gpair, g_gpair);
    cudaGetSymbolAddress((void**)&p_grh, g_grh);
    cudaGetSymbolAddress((void**)&p_z, g_z);

    cudaFuncSetAttribute(gate_kernel, cudaFuncAttributeMaxDynamicSharedMemorySize, 66560);
    cudaFuncSetAttribute(cand_kernel, cudaFuncAttributeMaxDynamicSharedMemorySize, 66560);

    // CSR build (rowptr enters zeroed; cleanup_kernel restores that at the end)
    hist_kernel<<<(E + 255) / 256, 256>>>(dst, E);              // 0
    scan_kernel<<<1, 1024>>>(N);                                // 1
    scatter_kernel<<<(E + 255) / 256, 256>>>(src, dst, ew, E);  // 2

    int gblocks = (N + 7) / 8;
    gconv_x<<<gblocks, 256>>>(x, N);                            // 3 (ncu-profiled slot)

    size_t N8 = (size_t)N * 8;
    int rb = (N + 63) / 64;
    dim3 gate_grid(rb, 2);
    size_t sm72  = (size_t)(72 * 64 + 64 * 72) * 4;    // 36864
    size_t sm128 = (size_t)(128 * 64 + 64 * 128) * 4;  // 65536

    for (int t = 0; t < 12; t++) {
        // ---- cell 0 ----  (gconv(h0_{t-1}) lives in gpair[:, 0:64] from prior dual pass)
        gate_kernel<<<gate_grid, 256, sm72>>>(p_gx + (size_t)t * N8, 8, 8,
                                              p_gpair, 128, 64,
                                              Wg0, bg0, p_h0, p_z, N);
        gconv64_h16<<<gblocks, 256>>>(N);
        cand_kernel<<<rb, 256, sm72>>>(p_gx + (size_t)t * N8, 8, 8,
                                       p_grh, 64, 64,
                                       Wc0, bc0, p_z, p_h0, 0, N);  // h0 <- new h0
        // ---- cell 1 ----
        gconv_dual_h16<<<gblocks, 256>>>(N);  // [gconv(h0_new) | gconv(h1)] from packed fp16
        gate_kernel<<<gate_grid, 256, sm128>>>(p_gpair, 128, 64,
                                               p_gpair + 64, 128, 64,
                                               Wg1, bg1, p_h1, p_z, N);
        gconv64_h16<<<gblocks, 256>>>(N);
        cand_kernel<<<rb, 256, sm128>>>(p_gpair, 128, 64,
                                        p_grh, 64, 64,
                                        Wc1, bc1, p_z, p_h1, 1, N);  // h1 <- new h1
    }

    out_kernel<<<gblocks, 256>>>(p_h1, Wout, bout, (float*)d_out, N);
    cleanup_kernel<<<512, 256>>>(N);
}